// round 11
// baseline (speedup 1.0000x reference)
#include <cuda_runtime.h>
#include <math.h>

#define NBC 128          // B*C
#define NQ 4             // quarters per bc
#define NBLK (NBC * NQ)  // 512 streaming blocks
#define EPSV 1e-5f

// ---------------------------------------------------------------------------
// Scratch (plain stores, fully overwritten each launch) + barrier state
// ---------------------------------------------------------------------------
__device__ float g_P1[NBC * 64];        // [bc][d]
__device__ float g_P2[NBLK * 64];       // [bc][q][h]
__device__ float g_P3[NBLK * 64];       // [bc][q][w]
__device__ float g_PQ[NBLK];            // [bc][q]
__device__ float g_W2[64 * 32];         // W2[h*32+r] = mean_s core2[r][h][s]
__device__ unsigned g_count = 0;        // arrival counter (reset by releaser)
__device__ unsigned g_gen   = 0;        // monotonic generation (never reset)

// ---------------------------------------------------------------------------
// Fused persistent kernel. 512 blocks x 256 threads, 4 blocks/SM co-resident
// (single wave: 512 <= 148*4). Block blk: bc = blk>>2, quarter q = blk&3 ->
// 4 chunks of 4 d-slices (256 KB of x).
// Phase 1: streaming reduction, register accumulation, loads in 2 batches of
//          8 float4 to fit the 64-reg/4-block budget.
// Phase 2: device-wide barrier (counter + generation; only blocks 0..127
//          wait -> deadlock-free at any occupancy).
// Phase 3: blocks 0..127 finalize one bc each: BN stats, projections, GELU.
// ---------------------------------------------------------------------------
__global__ void __launch_bounds__(256, 4) fused_kernel(
    const float* __restrict__ x, const float* __restrict__ gamma,
    const float* __restrict__ beta, const float* __restrict__ core1,
    const float* __restrict__ core2, const float* __restrict__ core3,
    float* __restrict__ out)
{
    const int blk  = blockIdx.x;      // 0..511
    const int bc   = blk >> 2;
    const int q    = blk & 3;
    const int tid  = threadIdx.x;
    const int lane = tid & 31;
    const int wid  = tid >> 5;
    const int r0   = tid >> 4;        // 0..15 (row phase)
    const int wq   = tid & 15;        // float4 column
    const unsigned FULL = 0xffffffffu;

    __shared__ unsigned s_gen0;
    __shared__ float sD[16];
    __shared__ float s2[64];
    __shared__ float s3[64];
    __shared__ float sq;

    if (tid == 0) s_gen0 = *(volatile unsigned*)&g_gen;
    if (tid < 16) sD[tid] = 0.f;
    if (tid < 64) { s2[tid] = 0.f; s3[tid] = 0.f; }
    if (tid == 1) sq = 0.f;
    __syncthreads();

    // ---- Phase 1: streaming reduction over 4 chunks (16 d-slices) --------
    float aH[4] = {0.f, 0.f, 0.f, 0.f};
    float aW[4] = {0.f, 0.f, 0.f, 0.f};
    float ssq = 0.f;

    const float4* xb0 = (const float4*)x + (size_t)bc * 65536 + (size_t)q * 16384;

#pragma unroll 1
    for (int j = 0; j < 4; j++) {
        const float4* xb = xb0 + j * 4096;
        float aD[4] = {0.f, 0.f, 0.f, 0.f};
#pragma unroll 1
        for (int g = 0; g < 2; g++) {
            float4 vv[8];
#pragma unroll
            for (int i = 0; i < 8; i++) {
                int ii = g * 8 + i;
                vv[i] = __ldcs(&xb[(r0 + 16 * ii) * 16 + wq]);
            }
#pragma unroll
            for (int i = 0; i < 8; i++) {
                int ii = g * 8 + i;
                float4 v = vv[i];
                float s = (v.x + v.y) + (v.z + v.w);
                aD[ii >> 2] += s;
                aH[ii & 3]  += s;
                aW[0] += v.x; aW[1] += v.y; aW[2] += v.z; aW[3] += v.w;
                ssq = fmaf(v.x, v.x, ssq);
                ssq = fmaf(v.y, v.y, ssq);
                ssq = fmaf(v.z, v.z, ssq);
                ssq = fmaf(v.w, v.w, ssq);
            }
        }
        // fold this chunk's aD into shared (warp tree + shared atomic)
#pragma unroll
        for (int k = 0; k < 4; k++) {
            float v = aD[k];
            v += __shfl_xor_sync(FULL, v, 16);
            v += __shfl_xor_sync(FULL, v, 8);
            v += __shfl_xor_sync(FULL, v, 4);
            v += __shfl_xor_sync(FULL, v, 2);
            v += __shfl_xor_sync(FULL, v, 1);
            if (lane == 0) atomicAdd(&sD[j * 4 + k], v);
        }
    }

    // ---- block epilogue: aH / aW / ssq ------------------------------------
    {
        float v = ssq;
        v += __shfl_xor_sync(FULL, v, 16);
        v += __shfl_xor_sync(FULL, v, 8);
        v += __shfl_xor_sync(FULL, v, 4);
        v += __shfl_xor_sync(FULL, v, 2);
        v += __shfl_xor_sync(FULL, v, 1);
        if (lane == 0) atomicAdd(&sq, v);
    }
    const int h0 = tid >> 4;   // h phase for this thread
#pragma unroll
    for (int k = 0; k < 4; k++) {
        float v = aH[k];
        v += __shfl_xor_sync(FULL, v, 8);
        v += __shfl_xor_sync(FULL, v, 4);
        v += __shfl_xor_sync(FULL, v, 2);
        v += __shfl_xor_sync(FULL, v, 1);
        if ((lane & 15) == 0) atomicAdd(&s2[h0 + 16 * k], v);
    }
#pragma unroll
    for (int k = 0; k < 4; k++) {
        float v = aW[k];
        v += __shfl_xor_sync(FULL, v, 16);
        if (lane < 16) atomicAdd(&s3[wq * 4 + k], v);
    }
    __syncthreads();

    // ---- store partials (plain stores, per-block private slots) -----------
    if (tid < 16) g_P1[bc * 64 + q * 16 + tid] = sD[tid];
    if (tid < 64) {
        g_P2[blk * 64 + tid] = s2[tid];
        g_P3[blk * 64 + tid] = s3[tid];
    }
    if (tid == 0) g_PQ[blk] = sq;

    // ---- W2 table: blocks 0..127, 16 entries each --------------------------
    if (blk < 128) {
        const int e  = tid >> 4;               // 0..15
        const int l  = tid & 15;
        const int te = blk * 16 + e;           // 0..2047
        const int h  = te >> 5, r = te & 31;
        float2 v2 = *(const float2*)(core2 + (size_t)r * 2048 + h * 32 + l * 2);
        float s = v2.x + v2.y;
        s += __shfl_xor_sync(FULL, s, 8);
        s += __shfl_xor_sync(FULL, s, 4);
        s += __shfl_xor_sync(FULL, s, 2);
        s += __shfl_xor_sync(FULL, s, 1);
        if (l == 0) g_W2[te] = s * (1.0f / 32.0f);
    }

    // ---- Phase 2: device-wide barrier -------------------------------------
    __threadfence();          // make this block's stores visible device-wide
    __syncthreads();
    if (tid == 0) {
        unsigned old = atomicAdd(&g_count, 1);
        if (old == (unsigned)(NBLK - 1)) {   // last arriver: reset + release
            g_count = 0u;
            __threadfence();
            atomicAdd(&g_gen, 1u);
        }
    }
    if (blk >= 128) return;          // non-finishers done

    if (tid == 0) {
        while (*(volatile unsigned*)&g_gen == s_gen0) { __nanosleep(64); }
    }
    __syncthreads();
    __threadfence();

    // ---- Phase 3: finalize for bc = blk ------------------------------------
    const int fc = blk & 15;         // channel
    const int fb = blk >> 4;         // batch
    __shared__ float sv[192];        // v1[0:64], v2[64:128], v3[128:192]
    __shared__ float wsum[8], wsq[8];
    __shared__ float s_scale, s_shift;

    if (tid < 64) {
        float a2 = 0.f, a3 = 0.f;
#pragma unroll
        for (int k = 0; k < 4; k++) {
            a2 += __ldcg(&g_P2[(blk * 4 + k) * 64 + tid]);
            a3 += __ldcg(&g_P3[(blk * 4 + k) * 64 + tid]);
        }
        sv[tid]       = __ldcg(&g_P1[blk * 64 + tid]);
        sv[64 + tid]  = a2;
        sv[128 + tid] = a3;
    }

    // channel stats: 512 P1 entries + 32 PQ entries for channel fc
    float ls = 0.f, lq = 0.f;
#pragma unroll
    for (int k = 0; k < 2; k++) {
        int i = tid + k * 256;              // 0..511
        int bp = i >> 6, d = i & 63;
        ls += __ldcg(&g_P1[(bp * 16 + fc) * 64 + d]);
    }
    if (tid < 32)
        lq = __ldcg(&g_PQ[((tid >> 2) * 16 + fc) * 4 + (tid & 3)]);
    ls += __shfl_xor_sync(FULL, ls, 16);
    ls += __shfl_xor_sync(FULL, ls, 8);
    ls += __shfl_xor_sync(FULL, ls, 4);
    ls += __shfl_xor_sync(FULL, ls, 2);
    ls += __shfl_xor_sync(FULL, ls, 1);
    lq += __shfl_xor_sync(FULL, lq, 16);
    lq += __shfl_xor_sync(FULL, lq, 8);
    lq += __shfl_xor_sync(FULL, lq, 4);
    lq += __shfl_xor_sync(FULL, lq, 2);
    lq += __shfl_xor_sync(FULL, lq, 1);
    if (lane == 0) { wsum[wid] = ls; wsq[wid] = lq; }
    __syncthreads();

    if (tid == 0) {
        float tot = 0.f, sqs = 0.f;
#pragma unroll
        for (int i = 0; i < 8; i++) { tot += wsum[i]; sqs += wsq[i]; }
        const float N = 2097152.0f;        // B*D*H*W
        float mean = tot / N;
        float var  = sqs / N - mean * mean;
        float inv  = rsqrtf(var + EPSV);
        float sc   = gamma[fc] * inv;
        s_scale = sc;
        s_shift = beta[fc] - mean * sc;
    }
    __syncthreads();

    if (tid < 64) {
        const float invHW = 1.0f / 4096.0f;
        float sc = s_scale, sh = s_shift;
        sv[tid]       = sv[tid]       * invHW * sc + sh;
        sv[64 + tid]  = sv[64 + tid]  * invHW * sc + sh;
        sv[128 + tid] = sv[128 + tid] * invHW * sc + sh;
    }
    __syncthreads();

    if (tid < 96) {
        const int mode = tid >> 5;   // 0: core1, 1: W2 table, 2: core3
        const int r    = tid & 31;
        float acc = 0.f;
        if (mode == 0) {
#pragma unroll
            for (int d = 0; d < 64; d++) acc = fmaf(sv[d], __ldg(&core1[d * 32 + r]), acc);
        } else if (mode == 1) {
#pragma unroll
            for (int h = 0; h < 64; h++) acc = fmaf(sv[64 + h], __ldcg(&g_W2[h * 32 + r]), acc);
        } else {
#pragma unroll
            for (int w = 0; w < 64; w++) acc = fmaf(sv[128 + w], __ldg(&core3[r * 64 + w]), acc);
        }
        float g = 0.5f * acc * (1.0f + erff(acc * 0.70710678118654752f));
        out[fb * 1536 + fc * 96 + tid] = g;
    }
}

// ---------------------------------------------------------------------------
// kernel_launch — inputs: x, gamma, beta, core1, core2, core3
// ---------------------------------------------------------------------------
extern "C" void kernel_launch(void* const* d_in, const int* in_sizes, int n_in,
                              void* d_out, int out_size) {
    const float* x     = (const float*)d_in[0];
    const float* gamma = (const float*)d_in[1];
    const float* beta  = (const float*)d_in[2];
    const float* core1 = (const float*)d_in[3];
    const float* core2 = (const float*)d_in[4];
    const float* core3 = (const float*)d_in[5];
    float* out = (float*)d_out;

    fused_kernel<<<NBLK, 256>>>(x, gamma, beta, core1, core2, core3, out);
}

// round 13
// speedup vs baseline: 1.0046x; 1.0046x over previous
#include <cuda_runtime.h>
#include <math.h>

#define NBC 128          // B*C
#define NQ 4             // quarters per bc
#define NBLK (NBC * NQ)  // 512 streaming blocks
#define EPSV 1e-5f

// ---------------------------------------------------------------------------
// Scratch (plain stores, fully overwritten each launch) + barrier state
// ---------------------------------------------------------------------------
__device__ float g_P1[NBC * 64];        // [bc][d]
__device__ float g_P2[NBLK * 64];       // [bc][q][h]
__device__ float g_P3[NBLK * 64];       // [bc][q][w]
__device__ float g_PQ[NBLK];            // [bc][q]
__device__ float g_W2[64 * 32];         // W2[h*32+r] = mean_s core2[r][h][s]
__device__ unsigned g_count = 0;        // arrival counter (reset by releaser)
__device__ unsigned g_gen   = 0;        // monotonic generation (never reset)

// ---------------------------------------------------------------------------
// Fused persistent kernel. 512 blocks x 256 threads, 4 blocks/SM co-resident
// (single wave: 512 <= 148*4). Block blk: bc = blk>>2, quarter q = blk&3 ->
// 4 chunks of 4 d-slices (256 KB of x).
// Phase 1: streaming reduction, register accumulation, loads in 2 batches of
//          8 float4 to fit the 64-reg/4-block budget.
// Phase 2: device-wide barrier (counter + generation; only blocks 0..127
//          wait -> deadlock-free at any occupancy).
// Phase 3: blocks 0..127 finalize one bc each: BN stats, projections, GELU.
// ---------------------------------------------------------------------------
__global__ void __launch_bounds__(256, 4) fused_kernel(
    const float* __restrict__ x, const float* __restrict__ gamma,
    const float* __restrict__ beta, const float* __restrict__ core1,
    const float* __restrict__ core2, const float* __restrict__ core3,
    float* __restrict__ out)
{
    const int blk  = blockIdx.x;      // 0..511
    const int bc   = blk >> 2;
    const int q    = blk & 3;
    const int tid  = threadIdx.x;
    const int lane = tid & 31;
    const int wid  = tid >> 5;
    const int r0   = tid >> 4;        // 0..15 (row phase)
    const int wq   = tid & 15;        // float4 column
    const unsigned FULL = 0xffffffffu;

    __shared__ unsigned s_gen0;
    __shared__ float sD[16];
    __shared__ float s2[64];
    __shared__ float s3[64];
    __shared__ float sq;

    if (tid == 0) s_gen0 = *(volatile unsigned*)&g_gen;
    if (tid < 16) sD[tid] = 0.f;
    if (tid < 64) { s2[tid] = 0.f; s3[tid] = 0.f; }
    if (tid == 1) sq = 0.f;
    __syncthreads();

    // ---- Phase 1: streaming reduction over 4 chunks (16 d-slices) --------
    float aH[4] = {0.f, 0.f, 0.f, 0.f};
    float aW[4] = {0.f, 0.f, 0.f, 0.f};
    float ssq = 0.f;

    const float4* xb0 = (const float4*)x + (size_t)bc * 65536 + (size_t)q * 16384;

#pragma unroll 1
    for (int j = 0; j < 4; j++) {
        const float4* xb = xb0 + j * 4096;
        float aD[4] = {0.f, 0.f, 0.f, 0.f};
#pragma unroll 1
        for (int g = 0; g < 2; g++) {
            float4 vv[8];
#pragma unroll
            for (int i = 0; i < 8; i++) {
                int ii = g * 8 + i;
                vv[i] = __ldcs(&xb[(r0 + 16 * ii) * 16 + wq]);
            }
#pragma unroll
            for (int i = 0; i < 8; i++) {
                int ii = g * 8 + i;
                float4 v = vv[i];
                float s = (v.x + v.y) + (v.z + v.w);
                aD[ii >> 2] += s;
                aH[ii & 3]  += s;
                aW[0] += v.x; aW[1] += v.y; aW[2] += v.z; aW[3] += v.w;
                ssq = fmaf(v.x, v.x, ssq);
                ssq = fmaf(v.y, v.y, ssq);
                ssq = fmaf(v.z, v.z, ssq);
                ssq = fmaf(v.w, v.w, ssq);
            }
        }
        // fold this chunk's aD into shared (warp tree + shared atomic)
#pragma unroll
        for (int k = 0; k < 4; k++) {
            float v = aD[k];
            v += __shfl_xor_sync(FULL, v, 16);
            v += __shfl_xor_sync(FULL, v, 8);
            v += __shfl_xor_sync(FULL, v, 4);
            v += __shfl_xor_sync(FULL, v, 2);
            v += __shfl_xor_sync(FULL, v, 1);
            if (lane == 0) atomicAdd(&sD[j * 4 + k], v);
        }
    }

    // ---- block epilogue: aH / aW / ssq ------------------------------------
    {
        float v = ssq;
        v += __shfl_xor_sync(FULL, v, 16);
        v += __shfl_xor_sync(FULL, v, 8);
        v += __shfl_xor_sync(FULL, v, 4);
        v += __shfl_xor_sync(FULL, v, 2);
        v += __shfl_xor_sync(FULL, v, 1);
        if (lane == 0) atomicAdd(&sq, v);
    }
    const int h0 = tid >> 4;   // h phase for this thread
#pragma unroll
    for (int k = 0; k < 4; k++) {
        float v = aH[k];
        v += __shfl_xor_sync(FULL, v, 8);
        v += __shfl_xor_sync(FULL, v, 4);
        v += __shfl_xor_sync(FULL, v, 2);
        v += __shfl_xor_sync(FULL, v, 1);
        if ((lane & 15) == 0) atomicAdd(&s2[h0 + 16 * k], v);
    }
#pragma unroll
    for (int k = 0; k < 4; k++) {
        float v = aW[k];
        v += __shfl_xor_sync(FULL, v, 16);
        if (lane < 16) atomicAdd(&s3[wq * 4 + k], v);
    }
    __syncthreads();

    // ---- store partials (plain stores, per-block private slots) -----------
    if (tid < 16) g_P1[bc * 64 + q * 16 + tid] = sD[tid];
    if (tid < 64) {
        g_P2[blk * 64 + tid] = s2[tid];
        g_P3[blk * 64 + tid] = s3[tid];
    }
    if (tid == 0) g_PQ[blk] = sq;

    // ---- W2 table: blocks 0..127, 16 entries each --------------------------
    if (blk < 128) {
        const int e  = tid >> 4;               // 0..15
        const int l  = tid & 15;
        const int te = blk * 16 + e;           // 0..2047
        const int h  = te >> 5, r = te & 31;
        float2 v2 = *(const float2*)(core2 + (size_t)r * 2048 + h * 32 + l * 2);
        float s = v2.x + v2.y;
        s += __shfl_xor_sync(FULL, s, 8);
        s += __shfl_xor_sync(FULL, s, 4);
        s += __shfl_xor_sync(FULL, s, 2);
        s += __shfl_xor_sync(FULL, s, 1);
        if (l == 0) g_W2[te] = s * (1.0f / 32.0f);
    }

    // ---- Phase 2: device-wide barrier -------------------------------------
    __threadfence();          // make this block's stores visible device-wide
    __syncthreads();
    if (tid == 0) {
        unsigned old = atomicAdd(&g_count, 1);
        if (old == (unsigned)(NBLK - 1)) {   // last arriver: reset + release
            g_count = 0u;
            __threadfence();
            atomicAdd(&g_gen, 1u);
        }
    }
    if (blk >= 128) return;          // non-finishers done

    if (tid == 0) {
        while (*(volatile unsigned*)&g_gen == s_gen0) { __nanosleep(64); }
    }
    __syncthreads();
    __threadfence();

    // ---- Phase 3: finalize for bc = blk ------------------------------------
    const int fc = blk & 15;         // channel
    const int fb = blk >> 4;         // batch
    __shared__ float sv[192];        // v1[0:64], v2[64:128], v3[128:192]
    __shared__ float wsum[8], wsq[8];
    __shared__ float s_scale, s_shift;

    if (tid < 64) {
        float a2 = 0.f, a3 = 0.f;
#pragma unroll
        for (int k = 0; k < 4; k++) {
            a2 += __ldcg(&g_P2[(blk * 4 + k) * 64 + tid]);
            a3 += __ldcg(&g_P3[(blk * 4 + k) * 64 + tid]);
        }
        sv[tid]       = __ldcg(&g_P1[blk * 64 + tid]);
        sv[64 + tid]  = a2;
        sv[128 + tid] = a3;
    }

    // channel stats: 512 P1 entries + 32 PQ entries for channel fc
    float ls = 0.f, lq = 0.f;
#pragma unroll
    for (int k = 0; k < 2; k++) {
        int i = tid + k * 256;              // 0..511
        int bp = i >> 6, d = i & 63;
        ls += __ldcg(&g_P1[(bp * 16 + fc) * 64 + d]);
    }
    if (tid < 32)
        lq = __ldcg(&g_PQ[((tid >> 2) * 16 + fc) * 4 + (tid & 3)]);
    ls += __shfl_xor_sync(FULL, ls, 16);
    ls += __shfl_xor_sync(FULL, ls, 8);
    ls += __shfl_xor_sync(FULL, ls, 4);
    ls += __shfl_xor_sync(FULL, ls, 2);
    ls += __shfl_xor_sync(FULL, ls, 1);
    lq += __shfl_xor_sync(FULL, lq, 16);
    lq += __shfl_xor_sync(FULL, lq, 8);
    lq += __shfl_xor_sync(FULL, lq, 4);
    lq += __shfl_xor_sync(FULL, lq, 2);
    lq += __shfl_xor_sync(FULL, lq, 1);
    if (lane == 0) { wsum[wid] = ls; wsq[wid] = lq; }
    __syncthreads();

    if (tid == 0) {
        float tot = 0.f, sqs = 0.f;
#pragma unroll
        for (int i = 0; i < 8; i++) { tot += wsum[i]; sqs += wsq[i]; }
        const float N = 2097152.0f;        // B*D*H*W
        float mean = tot / N;
        float var  = sqs / N - mean * mean;
        float inv  = rsqrtf(var + EPSV);
        float sc   = gamma[fc] * inv;
        s_scale = sc;
        s_shift = beta[fc] - mean * sc;
    }
    __syncthreads();

    if (tid < 64) {
        const float invHW = 1.0f / 4096.0f;
        float sc = s_scale, sh = s_shift;
        sv[tid]       = sv[tid]       * invHW * sc + sh;
        sv[64 + tid]  = sv[64 + tid]  * invHW * sc + sh;
        sv[128 + tid] = sv[128 + tid] * invHW * sc + sh;
    }
    __syncthreads();

    if (tid < 96) {
        const int mode = tid >> 5;   // 0: core1, 1: W2 table, 2: core3
        const int r    = tid & 31;
        float acc = 0.f;
        if (mode == 0) {
#pragma unroll
            for (int d = 0; d < 64; d++) acc = fmaf(sv[d], __ldg(&core1[d * 32 + r]), acc);
        } else if (mode == 1) {
#pragma unroll
            for (int h = 0; h < 64; h++) acc = fmaf(sv[64 + h], __ldcg(&g_W2[h * 32 + r]), acc);
        } else {
#pragma unroll
            for (int w = 0; w < 64; w++) acc = fmaf(sv[128 + w], __ldg(&core3[r * 64 + w]), acc);
        }
        float g = 0.5f * acc * (1.0f + erff(acc * 0.70710678118654752f));
        out[fb * 1536 + fc * 96 + tid] = g;
    }
}

// ---------------------------------------------------------------------------
// kernel_launch — inputs: x, gamma, beta, core1, core2, core3
// ---------------------------------------------------------------------------
extern "C" void kernel_launch(void* const* d_in, const int* in_sizes, int n_in,
                              void* d_out, int out_size) {
    const float* x     = (const float*)d_in[0];
    const float* gamma = (const float*)d_in[1];
    const float* beta  = (const float*)d_in[2];
    const float* core1 = (const float*)d_in[3];
    const float* core2 = (const float*)d_in[4];
    const float* core3 = (const float*)d_in[5];
    float* out = (float*)d_out;

    fused_kernel<<<NBLK, 256>>>(x, gamma, beta, core1, core2, core3, out);
}

// round 14
// speedup vs baseline: 1.0674x; 1.0625x over previous
#include <cuda_runtime.h>
#include <math.h>
#include <stdint.h>

#define NBC 128           // B*C
#define EPSV 1e-5f
#define NSTAGE 4
#define STAGE_BYTES 16384 // one d-slice: 64h x 64w x 4B
#define NSLICE 32         // d-slices per block (half of one bc)

// ---------------------------------------------------------------------------
// Scratch (plain stores, fully overwritten each launch) + barrier state
// ---------------------------------------------------------------------------
__device__ float g_P1[NBC * 64];        // [bc][d]
__device__ float g_P2[NBC * 2 * 64];    // [bc][half][h]
__device__ float g_P3[NBC * 2 * 64];    // [bc][half][w]
__device__ float g_PQ[NBC * 2];         // [bc][half]
__device__ float g_W2[64 * 32];         // W2[h*32+r] = mean_s core2[r][h][s]
__device__ unsigned g_count = 0;        // arrival counter (reset by releaser)
__device__ unsigned g_gen   = 0;        // monotonic generation (never reset)

__device__ __forceinline__ uint32_t smem_u32(const void* p) {
    uint32_t a;
    asm("{ .reg .u64 t; cvta.to.shared.u64 t, %1; cvt.u32.u64 %0, t; }"
        : "=r"(a) : "l"(p));
    return a;
}
__device__ __forceinline__ void mbar_init(uint32_t addr, uint32_t cnt) {
    asm volatile("mbarrier.init.shared.b64 [%0], %1;" :: "r"(addr), "r"(cnt) : "memory");
}
__device__ __forceinline__ void mbar_expect_tx(uint32_t addr, uint32_t bytes) {
    asm volatile("mbarrier.arrive.expect_tx.shared.b64 _, [%0], %1;"
                 :: "r"(addr), "r"(bytes) : "memory");
}
__device__ __forceinline__ void mbar_wait(uint32_t addr, uint32_t phase) {
    asm volatile(
        "{\n\t.reg .pred P;\n\t"
        "W%=: mbarrier.try_wait.parity.acquire.cta.shared::cta.b64 P, [%0], %1, 0x989680;\n\t"
        "@P bra D%=;\n\t"
        "bra W%=;\n\t"
        "D%=:\n\t}"
        :: "r"(addr), "r"(phase) : "memory");
}
__device__ __forceinline__ void bulk_g2s(uint32_t dst_smem, const void* src, uint32_t bytes,
                                         uint32_t mbar_addr) {
    asm volatile(
        "cp.async.bulk.shared::cta.global.mbarrier::complete_tx::bytes [%0], [%1], %2, [%3];"
        :: "r"(dst_smem), "l"(src), "r"(bytes), "r"(mbar_addr) : "memory");
}

// ---------------------------------------------------------------------------
// Fused persistent kernel. 256 blocks x 256 threads, 2/SM (smem-bound).
// Block blk: bc = blk>>1, half = blk&1 -> 32 d-slices (512 KB of x).
// Phase 1: cp.async.bulk pipeline (4 stages x 16 KB, 3 in flight) DRAM->smem,
//          consume via LDS.128. One d-slice per stage -> aD is one scalar per
//          stage (per-warp slot store, no atomics).
// Phase 2: device-wide barrier (counter + generation; only blocks 0..127
//          wait -> deadlock-free at any occupancy).
// Phase 3: blocks 0..127 finalize one bc each: BN stats, projections, GELU.
// ---------------------------------------------------------------------------
__global__ void __launch_bounds__(256) fused_kernel(
    const float* __restrict__ x, const float* __restrict__ gamma,
    const float* __restrict__ beta, const float* __restrict__ core1,
    const float* __restrict__ core2, const float* __restrict__ core3,
    float* __restrict__ out)
{
    extern __shared__ float4 dynbuf[];   // NSTAGE * 1024 float4 = 64 KB

    const int blk  = blockIdx.x;      // 0..255
    const int bc   = blk >> 1;
    const int half = blk & 1;
    const int tid  = threadIdx.x;
    const int lane = tid & 31;
    const int wid  = tid >> 5;
    const int wq   = tid & 15;        // float4 column phase (w-quad)
    const unsigned FULL = 0xffffffffu;

    __shared__ uint64_t mbar_s[NSTAGE];
    __shared__ unsigned s_gen0;
    __shared__ float sDw[8 * 32];     // [warp][slice] partial d sums
    __shared__ float s2[64];
    __shared__ float s3[64];
    __shared__ float sq;

    const uint32_t mb0 = smem_u32(&mbar_s[0]);

    if (tid == 0) {
        s_gen0 = *(volatile unsigned*)&g_gen;
#pragma unroll
        for (int s = 0; s < NSTAGE; s++) mbar_init(mb0 + 8 * s, 1);
        asm volatile("fence.proxy.async.shared::cta;" ::: "memory");
    }
    if (tid < 64) { s2[tid] = 0.f; s3[tid] = 0.f; }
    if (tid == 1) sq = 0.f;
    __syncthreads();

    // ---- Phase 1: bulk-async pipeline over 32 d-slices ---------------------
    const char* xsrc = (const char*)x + (size_t)bc * 1048576 + (size_t)half * 524288;
    const uint32_t buf0 = smem_u32(dynbuf);

    if (tid == 0) {
#pragma unroll
        for (int p = 0; p < NSTAGE - 1; p++) {   // 3 stages in flight
            mbar_expect_tx(mb0 + 8 * p, STAGE_BYTES);
            bulk_g2s(buf0 + p * STAGE_BYTES, xsrc + (size_t)p * STAGE_BYTES,
                     STAGE_BYTES, mb0 + 8 * p);
        }
    }

    float aH[4] = {0.f, 0.f, 0.f, 0.f};
    float aW[4] = {0.f, 0.f, 0.f, 0.f};
    float ssq = 0.f;

#pragma unroll 1
    for (int s = 0; s < NSLICE; s++) {
        const int slot = s & 3;
        mbar_wait(mb0 + 8 * slot, (s >> 2) & 1);

        const float4* buf = dynbuf + slot * 1024;
        float ls = 0.f;
#pragma unroll
        for (int i = 0; i < 4; i++) {
            float4 v = buf[tid + 256 * i];       // h = (tid>>4) + 16*i, w-quad = wq
            float sm = (v.x + v.y) + (v.z + v.w);
            ls += sm;
            aH[i] += sm;
            aW[0] += v.x; aW[1] += v.y; aW[2] += v.z; aW[3] += v.w;
            ssq = fmaf(v.x, v.x, ssq);
            ssq = fmaf(v.y, v.y, ssq);
            ssq = fmaf(v.z, v.z, ssq);
            ssq = fmaf(v.w, v.w, ssq);
        }
        // this slice's d-sum: full-warp tree, per-warp slot (no atomics)
        ls += __shfl_xor_sync(FULL, ls, 16);
        ls += __shfl_xor_sync(FULL, ls, 8);
        ls += __shfl_xor_sync(FULL, ls, 4);
        ls += __shfl_xor_sync(FULL, ls, 2);
        ls += __shfl_xor_sync(FULL, ls, 1);
        if (lane == 0) sDw[wid * 32 + s] = ls;

        __syncthreads();   // all consumed slot (s-1)&3 before tid0 refills it
        if (tid == 0 && s + 3 < NSLICE) {
            const int n = s + 3, ns = n & 3;
            mbar_expect_tx(mb0 + 8 * ns, STAGE_BYTES);
            bulk_g2s(buf0 + ns * STAGE_BYTES, xsrc + (size_t)n * STAGE_BYTES,
                     STAGE_BYTES, mb0 + 8 * ns);
        }
    }

    // ---- block epilogue: ssq / aH / aW -------------------------------------
    {
        float v = ssq;
        v += __shfl_xor_sync(FULL, v, 16);
        v += __shfl_xor_sync(FULL, v, 8);
        v += __shfl_xor_sync(FULL, v, 4);
        v += __shfl_xor_sync(FULL, v, 2);
        v += __shfl_xor_sync(FULL, v, 1);
        if (lane == 0) atomicAdd(&sq, v);
    }
    const int h0 = tid >> 4;
#pragma unroll
    for (int k = 0; k < 4; k++) {
        float v = aH[k];
        v += __shfl_xor_sync(FULL, v, 8);
        v += __shfl_xor_sync(FULL, v, 4);
        v += __shfl_xor_sync(FULL, v, 2);
        v += __shfl_xor_sync(FULL, v, 1);
        if ((lane & 15) == 0) atomicAdd(&s2[h0 + 16 * k], v);
    }
#pragma unroll
    for (int k = 0; k < 4; k++) {
        float v = aW[k];
        v += __shfl_xor_sync(FULL, v, 16);
        if (lane < 16) atomicAdd(&s3[wq * 4 + k], v);
    }
    __syncthreads();

    // ---- store partials -----------------------------------------------------
    if (tid < 32) {
        float a = 0.f;
#pragma unroll
        for (int w = 0; w < 8; w++) a += sDw[w * 32 + tid];
        g_P1[bc * 64 + half * 32 + tid] = a;
    }
    if (tid < 64) {
        g_P2[blk * 64 + tid] = s2[tid];
        g_P3[blk * 64 + tid] = s3[tid];
    }
    if (tid == 0) g_PQ[blk] = sq;

    // ---- W2 table: blocks 0..127, 16 entries each ---------------------------
    if (blk < 128) {
        const int e  = tid >> 4;
        const int l  = tid & 15;
        const int te = blk * 16 + e;           // 0..2047
        const int h  = te >> 5, r = te & 31;
        float2 v2 = *(const float2*)(core2 + (size_t)r * 2048 + h * 32 + l * 2);
        float s = v2.x + v2.y;
        s += __shfl_xor_sync(FULL, s, 8);
        s += __shfl_xor_sync(FULL, s, 4);
        s += __shfl_xor_sync(FULL, s, 2);
        s += __shfl_xor_sync(FULL, s, 1);
        if (l == 0) g_W2[te] = s * (1.0f / 32.0f);
    }

    // ---- Phase 2: device-wide barrier ---------------------------------------
    __threadfence();
    __syncthreads();
    if (tid == 0) {
        unsigned old = atomicAdd(&g_count, 1);
        if (old == 255u) {
            g_count = 0u;
            __threadfence();
            atomicAdd(&g_gen, 1u);
        }
    }
    if (blk >= 128) return;

    if (tid == 0) {
        while (*(volatile unsigned*)&g_gen == s_gen0) { __nanosleep(64); }
    }
    __syncthreads();
    __threadfence();

    // ---- Phase 3: finalize for bc = blk --------------------------------------
    const int fc = blk & 15;
    const int fb = blk >> 4;
    __shared__ float sv[192];
    __shared__ float wsum[8], wsq[8];
    __shared__ float s_scale, s_shift;

    if (tid < 64) {
        sv[tid]       = __ldcg(&g_P1[blk * 64 + tid]);
        sv[64 + tid]  = __ldcg(&g_P2[(blk * 2) * 64 + tid]) + __ldcg(&g_P2[(blk * 2 + 1) * 64 + tid]);
        sv[128 + tid] = __ldcg(&g_P3[(blk * 2) * 64 + tid]) + __ldcg(&g_P3[(blk * 2 + 1) * 64 + tid]);
    }

    float ls = 0.f, lq = 0.f;
#pragma unroll
    for (int k = 0; k < 2; k++) {
        int i = tid + k * 256;              // 0..511
        int bp = i >> 6, d = i & 63;
        ls += __ldcg(&g_P1[(bp * 16 + fc) * 64 + d]);
    }
    if (tid < 16)
        lq = __ldcg(&g_PQ[((tid >> 1) * 16 + fc) * 2 + (tid & 1)]);
    ls += __shfl_xor_sync(FULL, ls, 16);
    ls += __shfl_xor_sync(FULL, ls, 8);
    ls += __shfl_xor_sync(FULL, ls, 4);
    ls += __shfl_xor_sync(FULL, ls, 2);
    ls += __shfl_xor_sync(FULL, ls, 1);
    lq += __shfl_xor_sync(FULL, lq, 16);
    lq += __shfl_xor_sync(FULL, lq, 8);
    lq += __shfl_xor_sync(FULL, lq, 4);
    lq += __shfl_xor_sync(FULL, lq, 2);
    lq += __shfl_xor_sync(FULL, lq, 1);
    if (lane == 0) { wsum[wid] = ls; wsq[wid] = lq; }
    __syncthreads();

    if (tid == 0) {
        float tot = 0.f, sqs = 0.f;
#pragma unroll
        for (int i = 0; i < 8; i++) { tot += wsum[i]; sqs += wsq[i]; }
        const float N = 2097152.0f;        // B*D*H*W
        float mean = tot / N;
        float var  = sqs / N - mean * mean;
        float inv  = rsqrtf(var + EPSV);
        float sc   = gamma[fc] * inv;
        s_scale = sc;
        s_shift = beta[fc] - mean * sc;
    }
    __syncthreads();

    if (tid < 64) {
        const float invHW = 1.0f / 4096.0f;
        float sc = s_scale, sh = s_shift;
        sv[tid]       = sv[tid]       * invHW * sc + sh;
        sv[64 + tid]  = sv[64 + tid]  * invHW * sc + sh;
        sv[128 + tid] = sv[128 + tid] * invHW * sc + sh;
    }
    __syncthreads();

    if (tid < 96) {
        const int mode = tid >> 5;
        const int r    = tid & 31;
        float acc = 0.f;
        if (mode == 0) {
#pragma unroll
            for (int d = 0; d < 64; d++) acc = fmaf(sv[d], __ldg(&core1[d * 32 + r]), acc);
        } else if (mode == 1) {
#pragma unroll
            for (int h = 0; h < 64; h++) acc = fmaf(sv[64 + h], __ldcg(&g_W2[h * 32 + r]), acc);
        } else {
#pragma unroll
            for (int w = 0; w < 64; w++) acc = fmaf(sv[128 + w], __ldg(&core3[r * 64 + w]), acc);
        }
        float g = 0.5f * acc * (1.0f + erff(acc * 0.70710678118654752f));
        out[fb * 1536 + fc * 96 + tid] = g;
    }
}

// ---------------------------------------------------------------------------
// kernel_launch — inputs: x, gamma, beta, core1, core2, core3
// ---------------------------------------------------------------------------
extern "C" void kernel_launch(void* const* d_in, const int* in_sizes, int n_in,
                              void* d_out, int out_size) {
    const float* x     = (const float*)d_in[0];
    const float* gamma = (const float*)d_in[1];
    const float* beta  = (const float*)d_in[2];
    const float* core1 = (const float*)d_in[3];
    const float* core2 = (const float*)d_in[4];
    const float* core3 = (const float*)d_in[5];
    float* out = (float*)d_out;

    const int dyn = NSTAGE * STAGE_BYTES;   // 64 KB
    cudaFuncSetAttribute(fused_kernel, cudaFuncAttributeMaxDynamicSharedMemorySize, dyn);
    fused_kernel<<<256, 256, dyn>>>(x, gamma, beta, core1, core2, core3, out);
}